// round 17
// baseline (speedup 1.0000x reference)
#include <cuda_runtime.h>
#include <cuda_bf16.h>
#include <cstdint>

#define NATOMS 6144
#define F 128
#define G 48
#define MTILES 48              // 48 m-tiles of 128 atoms
#define SPLIT 24               // pair blocks per graph
#define MAXC 256
#define KE_CONST 14.3996f

// smem layout (bytes): bf16 tiles with 136-element (272B) row stride
#define RS 136
#define TILE_B (128 * RS * 2)          // 34816
#define SM_AHI  0
#define SM_ALO  (SM_AHI + TILE_B)
#define SM_BHI  (SM_ALO + TILE_B)
#define SM_BLO  (SM_BHI + TILE_B)
#define SM_B1   (SM_BLO + TILE_B)      // 128 floats
#define SM_W2A  (SM_B1  + 512)
#define SM_W2B  (SM_W2A + 512)
#define SM_RED0 (SM_W2B + 512)
#define SM_RED1 (SM_RED0 + 512)
#define SM_TOTAL (SM_RED1 + 512)       // 141824

// ---------------- scratch ----------------
__device__ float    g_q[NATOMS];
__device__ float    g_sc6[NATOMS];
__device__ float    g_r3[NATOMS];
__device__ int      g_start[G];
__device__ int      g_cnt[G];
__device__ double   g_esum;
__device__ unsigned g_done;

__device__ __forceinline__ float softplusf(float x) {
    return fmaxf(x, 0.0f) + log1pf(expf(-fabsf(x)));
}
__device__ __forceinline__ float siluf(float x) {
    return x / (1.0f + expf(-x));
}
__device__ __forceinline__ uint32_t smem_to_u32(const void* p) {
    uint32_t addr;
    asm("{ .reg .u64 tmp; cvta.to.shared.u64 tmp, %1; cvt.u32.u64 %0, tmp; }"
        : "=r"(addr) : "l"(p));
    return addr;
}
__device__ __forceinline__ uint32_t pack_bf16x2(__nv_bfloat16 a, __nv_bfloat16 b) {
    return (uint32_t)__bfloat16_as_ushort(a) | ((uint32_t)__bfloat16_as_ushort(b) << 16);
}
__device__ __forceinline__ void ldm4(uint32_t r[4], uint32_t addr) {
    asm volatile("ldmatrix.sync.aligned.m8n8.x4.shared.b16 {%0,%1,%2,%3}, [%4];"
        : "=r"(r[0]), "=r"(r[1]), "=r"(r[2]), "=r"(r[3]) : "r"(addr));
}
__device__ __forceinline__ void mma16816(float c[4], const uint32_t a[4],
                                         uint32_t b0, uint32_t b1) {
    asm volatile(
        "mma.sync.aligned.m16n8k16.row.col.f32.bf16.bf16.f32 "
        "{%0,%1,%2,%3}, {%4,%5,%6,%7}, {%8,%9}, {%0,%1,%2,%3};"
        : "+f"(c[0]), "+f"(c[1]), "+f"(c[2]), "+f"(c[3])
        : "r"(a[0]), "r"(a[1]), "r"(a[2]), "r"(a[3]), "r"(b0), "r"(b1));
}
__device__ __forceinline__ float rsq_approx(float x) {
    float r; asm("rsqrt.approx.f32 %0, %1;" : "=f"(r) : "f"(x)); return r;
}

// ================= K1: MLP via warp-level bf16 MMA (hi/lo 3-term) =========
// grid = 2*MTILES + 1 = 97 blocks x 256 threads.
// bid < 96: head = bid/48, m-tile = bid%48 (128 atoms). Last block: service.
// 8 warps as 4(m) x 2(n): warp = rows [wm*32,+32), cols [wn*64,+64).
__global__ __launch_bounds__(256) void mlp_mma_kernel(
    const float* __restrict__ h0,
    const float* __restrict__ qW1, const float* __restrict__ qb1,
    const float* __restrict__ qW2,
    const float* __restrict__ vW1, const float* __restrict__ vb1,
    const float* __restrict__ vW2, const float* __restrict__ vb2,
    const int*   __restrict__ batch)
{
    const int bid = blockIdx.x;
    const int tid = threadIdx.x;

    if (bid == 2 * MTILES) {
        if (tid == 0) { g_esum = 0.0; g_done = 0u; }
        __shared__ int ss[G + 1];
        if (tid <= G) {
            int lo = 0, hi = NATOMS;
            while (lo < hi) {
                int m = (lo + hi) >> 1;
                if (batch[m] < tid) lo = m + 1; else hi = m;
            }
            ss[tid] = lo;
        }
        __syncthreads();
        if (tid < G) { g_start[tid] = ss[tid]; g_cnt[tid] = ss[tid + 1] - ss[tid]; }
        return;
    }

    extern __shared__ char smem[];
    const int head  = bid / MTILES;
    const int mbase = (bid % MTILES) * F;

    const float* __restrict__ W1 = head ? vW1 : qW1;
    const float* __restrict__ B1 = head ? vb1 : qb1;

    float* b1s  = (float*)(smem + SM_B1);
    float* w2as = (float*)(smem + SM_W2A);
    float* w2bs = (float*)(smem + SM_W2B);
    float* red0 = (float*)(smem + SM_RED0);
    float* red1 = (float*)(smem + SM_RED1);

    if (tid < F) {
        b1s[tid] = B1[tid];
        if (head) { w2as[tid] = vW2[2 * tid]; w2bs[tid] = vW2[2 * tid + 1]; }
        else      { w2as[tid] = qW2[tid];     w2bs[tid] = 0.0f; }
    }

    // ---- A convert: h0 tile -> Ahi/Alo [m][k] bf16 ----
    {
        const int row = tid >> 1;
        const int seg = (tid & 1) * 64;
        const float4* src = (const float4*)(h0 + (size_t)(mbase + row) * F + seg);
        uint32_t* dhi = (uint32_t*)(smem + SM_AHI) + (row * RS + seg) / 2;
        uint32_t* dlo = (uint32_t*)(smem + SM_ALO) + (row * RS + seg) / 2;
#pragma unroll
        for (int j = 0; j < 16; j++) {
            float4 v = src[j];
            __nv_bfloat16 hx = __float2bfloat16(v.x), hy = __float2bfloat16(v.y);
            __nv_bfloat16 hz = __float2bfloat16(v.z), hw = __float2bfloat16(v.w);
            __nv_bfloat16 lx = __float2bfloat16(v.x - __bfloat162float(hx));
            __nv_bfloat16 ly = __float2bfloat16(v.y - __bfloat162float(hy));
            __nv_bfloat16 lz = __float2bfloat16(v.z - __bfloat162float(hz));
            __nv_bfloat16 lw = __float2bfloat16(v.w - __bfloat162float(hw));
            dhi[2 * j + 0] = pack_bf16x2(hx, hy);
            dhi[2 * j + 1] = pack_bf16x2(hz, hw);
            dlo[2 * j + 0] = pack_bf16x2(lx, ly);
            dlo[2 * j + 1] = pack_bf16x2(lz, lw);
        }
    }

    // ---- B convert + transpose: W1[k][n] -> Bhi/Blo [n][k] bf16 ----
    {
        const int k    = tid >> 1;
        const int nseg = (tid & 1) * 64;
        const float4* src = (const float4*)(W1 + (size_t)k * F + nseg);
        __nv_bfloat16* bhi = (__nv_bfloat16*)(smem + SM_BHI);
        __nv_bfloat16* blo = (__nv_bfloat16*)(smem + SM_BLO);
#pragma unroll
        for (int j = 0; j < 16; j++) {
            float4 v = src[j];
            float vv[4] = {v.x, v.y, v.z, v.w};
#pragma unroll
            for (int e = 0; e < 4; e++) {
                int n = nseg + 4 * j + e;
                __nv_bfloat16 hb = __float2bfloat16(vv[e]);
                __nv_bfloat16 lb = __float2bfloat16(vv[e] - __bfloat162float(hb));
                bhi[n * RS + k] = hb;
                blo[n * RS + k] = lb;
            }
        }
    }
    __syncthreads();

    // ---- MMA mainloop ----
    const int wid = tid >> 5, lane = tid & 31;
    const int wm = wid >> 1, wn = wid & 1;
    const int m0 = wm * 32;

    float acc[2][8][4];
#pragma unroll
    for (int mt = 0; mt < 2; mt++)
#pragma unroll
        for (int nt = 0; nt < 8; nt++)
#pragma unroll
            for (int e = 0; e < 4; e++) acc[mt][nt][e] = 0.0f;

    const uint32_t sb = smem_to_u32(smem);
    uint32_t aHi[2], aLo[2], bHi[4], bLo[4];
#pragma unroll
    for (int mt = 0; mt < 2; mt++) {
        int rowA = m0 + mt * 16 + (lane & 15);
        int colA = (lane >> 4) * 8;
        aHi[mt] = sb + SM_AHI + (rowA * RS + colA) * 2;
        aLo[mt] = sb + SM_ALO + (rowA * RS + colA) * 2;
    }
#pragma unroll
    for (int p = 0; p < 4; p++) {
        int nB = wn * 64 + p * 16 + (lane & 7) + ((lane >> 4) & 1) * 8;
        int kB = ((lane >> 3) & 1) * 8;
        bHi[p] = sb + SM_BHI + (nB * RS + kB) * 2;
        bLo[p] = sb + SM_BLO + (nB * RS + kB) * 2;
    }

#pragma unroll
    for (int s = 0; s < 8; s++) {
        uint32_t ah[2][4], al[2][4], bh[4][4], bl[4][4];
#pragma unroll
        for (int mt = 0; mt < 2; mt++) {
            ldm4(ah[mt], aHi[mt]); aHi[mt] += 32;
            ldm4(al[mt], aLo[mt]); aLo[mt] += 32;
        }
#pragma unroll
        for (int p = 0; p < 4; p++) {
            ldm4(bh[p], bHi[p]); bHi[p] += 32;
            ldm4(bl[p], bLo[p]); bLo[p] += 32;
        }
#pragma unroll
        for (int mt = 0; mt < 2; mt++) {
#pragma unroll
            for (int p = 0; p < 4; p++) {
                mma16816(acc[mt][2 * p],     ah[mt], bh[p][0], bh[p][1]);
                mma16816(acc[mt][2 * p],     al[mt], bh[p][0], bh[p][1]);
                mma16816(acc[mt][2 * p],     ah[mt], bl[p][0], bl[p][1]);
                mma16816(acc[mt][2 * p + 1], ah[mt], bh[p][2], bh[p][3]);
                mma16816(acc[mt][2 * p + 1], al[mt], bh[p][2], bh[p][3]);
                mma16816(acc[mt][2 * p + 1], ah[mt], bl[p][2], bl[p][3]);
            }
        }
    }

    // ---- epilogue: silu + layer-2 dot + reduce ----
    float s0p[2][2], s1p[2][2];
#pragma unroll
    for (int mt = 0; mt < 2; mt++)
#pragma unroll
        for (int rh = 0; rh < 2; rh++) { s0p[mt][rh] = 0.f; s1p[mt][rh] = 0.f; }

#pragma unroll
    for (int mt = 0; mt < 2; mt++)
#pragma unroll
        for (int nt = 0; nt < 8; nt++)
#pragma unroll
            for (int e = 0; e < 4; e++) {
                int n = wn * 64 + nt * 8 + (lane & 3) * 2 + (e & 1);
                float h = siluf(acc[mt][nt][e] + b1s[n]);
                s0p[mt][e >> 1] += h * w2as[n];
                s1p[mt][e >> 1] += h * w2bs[n];
            }

#pragma unroll
    for (int mt = 0; mt < 2; mt++)
#pragma unroll
        for (int rh = 0; rh < 2; rh++) {
            float v0 = s0p[mt][rh], v1 = s1p[mt][rh];
            v0 += __shfl_xor_sync(0xFFFFFFFFu, v0, 1);
            v0 += __shfl_xor_sync(0xFFFFFFFFu, v0, 2);
            v1 += __shfl_xor_sync(0xFFFFFFFFu, v1, 1);
            v1 += __shfl_xor_sync(0xFFFFFFFFu, v1, 2);
            s0p[mt][rh] = v0; s1p[mt][rh] = v1;
        }

    if ((lane & 3) == 0 && wn == 0) {
#pragma unroll
        for (int mt = 0; mt < 2; mt++)
#pragma unroll
            for (int rh = 0; rh < 2; rh++) {
                int r = m0 + mt * 16 + (lane >> 2) + rh * 8;
                red0[r] = s0p[mt][rh];
                red1[r] = s1p[mt][rh];
            }
    }
    __syncthreads();
    if ((lane & 3) == 0 && wn == 1) {
#pragma unroll
        for (int mt = 0; mt < 2; mt++)
#pragma unroll
            for (int rh = 0; rh < 2; rh++) {
                int r = m0 + mt * 16 + (lane >> 2) + rh * 8;
                red0[r] += s0p[mt][rh];
                red1[r] += s1p[mt][rh];
            }
    }
    __syncthreads();

    if (tid < F) {
        int atom = mbase + tid;
        float s0 = red0[tid], s1 = red1[tid];
        if (head == 0) {
            g_q[atom] = s0;
        } else {
            float c6 = softplusf(s0 + vb2[0]);
            float rv = softplusf(s1 + vb2[1]);
            g_sc6[atom] = sqrtf(c6);
            g_r3[atom]  = rv * rv * rv;
        }
    }
}

// ================= K2: pairwise (SPLIT 24, rsqrt, 2x unroll) ==============
__global__ __launch_bounds__(128) void pair_kernel(
    const float* __restrict__ pos,
    const float* __restrict__ sigma,
    float* __restrict__ out)
{
    __shared__ float sx[MAXC], sy[MAXC], sz[MAXC];
    __shared__ float sq[MAXC], sc[MAXC], sr[MAXC];
    __shared__ float wred[4];
    __shared__ float s_qm;

    const int bid = blockIdx.x;
    const int g  = bid / SPLIT;
    const int sp = bid % SPLIT;
    const int tid = threadIdx.x;
    const int lane = tid & 31;
    const int wrp  = tid >> 5;

    const int s = g_start[g];
    const int c = g_cnt[g];

    float qacc = 0.f;
    for (int t = tid; t < c; t += 128) {
        int j = s + t;
        sx[t] = pos[3 * j + 0];
        sy[t] = pos[3 * j + 1];
        sz[t] = pos[3 * j + 2];
        float qv = g_q[j];
        sq[t] = qv;  qacc += qv;
        sc[t] = g_sc6[j];
        sr[t] = g_r3[j];
    }
#pragma unroll
    for (int o = 16; o > 0; o >>= 1) qacc += __shfl_xor_sync(0xFFFFFFFFu, qacc, o);
    if (lane == 0) wred[wrp] = qacc;
    __syncthreads();
    if (tid == 0) s_qm = (wred[0] + wred[1] + wred[2] + wred[3]) / fmaxf((float)c, 1.0f);
    __syncthreads();
    const float qm = s_qm;
    for (int t = tid; t < c; t += 128) sq[t] -= qm;
    __syncthreads();

    const float invs = 1.0f / (1.41421356f * sigma[0]);
    const int wg = wrp + sp * 4;

    float eel = 0.f, evd = 0.f;
    float eel2 = 0.f, evd2 = 0.f;

// NOTE: macro-local variable named jj to avoid shadowing the caller's j
#define PAIR_BODY(JJ, EE, EV)                                               \
    {                                                                        \
        const int jj = (JJ);                                                 \
        float dx = px - sx[jj];                                              \
        float dy = py - sy[jj];                                              \
        float dz = pz - sz[jj];                                              \
        float dsq = dx * dx + dy * dy + dz * dz;                             \
        float ssum = dsq + 1e-8f;                                            \
        float rsq = rsq_approx(ssum);                                        \
        float dist = ssum * rsq;                                             \
        float invd = fmaf(-1e-8f * rsq, rsq, rsq);                           \
        EE += qi * sq[jj] * erff(dist * invs) * invd;                        \
        float damp = dsq * dsq * dsq + r3i * sr[jj];                         \
        EV -= __fdividef(c6i * sc[jj], damp + 1e-8f);                        \
    }

    for (int i = wg; i < c; i += SPLIT * 4) {
        float px = sx[i], py = sy[i], pz = sz[i];
        float qi = sq[i], c6i = sc[i], r3i = sr[i];
        int j = i + 1 + lane;
        for (; j + 32 < c; j += 64) {
            PAIR_BODY(j, eel, evd);
            PAIR_BODY(j + 32, eel2, evd2);
        }
        if (j < c) PAIR_BODY(j, eel, evd);
    }
#undef PAIR_BODY

    float tot = KE_CONST * (eel + eel2) + (evd + evd2);  // 2 * 0.5 = 1
#pragma unroll
    for (int o = 16; o > 0; o >>= 1) tot += __shfl_down_sync(0xFFFFFFFFu, tot, o);
    if (lane == 0) wred[wrp] = tot;
    __syncthreads();
    if (tid == 0) {
        double bsum = (double)(wred[0] + wred[1] + wred[2] + wred[3]);
        atomicAdd(&g_esum, bsum);
        __threadfence();
        unsigned t = atomicAdd(&g_done, 1u);
        if (t == gridDim.x - 1) {
            g_done = 0u;
            double total = atomicAdd(&g_esum, 0.0);
            out[0] = (float)total;
        }
    }
}

// ---------------- launch ----------------
extern "C" void kernel_launch(void* const* d_in, const int* in_sizes, int n_in,
                              void* d_out, int out_size) {
    const float* h0    = (const float*)d_in[0];
    const float* pos   = (const float*)d_in[2];
    const float* qW1   = (const float*)d_in[3];
    const float* qb1   = (const float*)d_in[4];
    const float* qW2   = (const float*)d_in[5];
    const float* sigma = (const float*)d_in[6];
    const float* vW1   = (const float*)d_in[7];
    const float* vb1   = (const float*)d_in[8];
    const float* vW2   = (const float*)d_in[9];
    const float* vb2   = (const float*)d_in[10];
    const int*   batch = (const int*)d_in[11];

    cudaFuncSetAttribute(mlp_mma_kernel,
                         cudaFuncAttributeMaxDynamicSharedMemorySize, SM_TOTAL);

    mlp_mma_kernel<<<2 * MTILES + 1, 256, SM_TOTAL>>>(h0, qW1, qb1, qW2,
                                                      vW1, vb1, vW2, vb2, batch);
    pair_kernel<<<G * SPLIT, 128>>>(pos, sigma, (float*)d_out);
}